// round 17
// baseline (speedup 1.0000x reference)
#include <cuda_runtime.h>
#include <cstdint>

// QINCo: D=128, M=8, K=256, L=2, H=256, BS=1024
#define Dq   128
#define Mq   8
#define Kq   256
#define Hq   256
#define BSq  1024
#define NROW (BSq * Kq)

#define OUT_CODES (BSq * Dq)
#define OUT_SIDE  (OUT_CODES + BSq * Mq)

// ---------------- device scratch (static, no allocs) ----------------
__device__ float g_xhat[BSq * Dq];
__device__ float g_CkAll[(Mq - 1) * Kq * Dq];
__device__ float g_A0All[(Mq - 1) * Kq * Hq];
__device__ float g_Xb[BSq * Dq];
__device__ float g_B0[BSq * Hq];
__device__ float g_Z1[NROW * Dq];
__device__ float g_H1[NROW * Hq];
__device__ float g_ZF[NROW * Dq];
__device__ float g_dist[NROW];

// ---------------- packed f32x2 helpers (prep kernels) ----------------
__device__ __forceinline__ void ffma2(unsigned long long& d, unsigned long long a, unsigned long long b) {
    asm("fma.rn.f32x2 %0, %1, %2, %0;" : "+l"(d) : "l"(a), "l"(b));
}
__device__ __forceinline__ unsigned long long bcast2(float v) {
    unsigned long long r;
    asm("mov.b64 %0, {%1, %1};" : "=l"(r) : "f"(v));
    return r;
}
__device__ __forceinline__ float2 unpk2(unsigned long long v) {
    float lo, hi;
    asm("mov.b64 {%0, %1}, %2;" : "=f"(lo), "=f"(hi) : "l"(v));
    return make_float2(lo, hi);
}

#define INNER_STEP(Rsrc, Wsrc)                                                  \
    do {                                                                        \
        float4 a0 = *(const float4*)(&(Rsrc)[h][ty * 8]);                       \
        float4 a1 = *(const float4*)(&(Rsrc)[h][ty * 8 + 4]);                   \
        ulonglong2 wv0 = *(const ulonglong2*)(&(Wsrc)[h][tx * 8]);              \
        ulonglong2 wv1 = *(const ulonglong2*)(&(Wsrc)[h][tx * 8 + 4]);          \
        unsigned long long ap[8] = {bcast2(a0.x), bcast2(a0.y), bcast2(a0.z),   \
                                    bcast2(a0.w), bcast2(a1.x), bcast2(a1.y),   \
                                    bcast2(a1.z), bcast2(a1.w)};                \
        unsigned long long wp[4] = {wv0.x, wv0.y, wv1.x, wv1.y};                \
        _Pragma("unroll")                                                       \
        for (int i = 0; i < 8; i++) {                                           \
            ffma2(acc[i][0], ap[i], wp[0]);                                     \
            ffma2(acc[i][1], ap[i], wp[1]);                                     \
            ffma2(acc[i][2], ap[i], wp[2]);                                     \
            ffma2(acc[i][3], ap[i], wp[3]);                                     \
        }                                                                       \
    } while (0)

// ---------------- tf32 split + mma.sync (base ISA, sm_80+) ----------------
__device__ __forceinline__ void split_tf32(float x, unsigned& hi, unsigned& lo) {
    unsigned h;
    asm("cvt.rna.tf32.f32 %0, %1;" : "=r"(h) : "f"(x));
    float r = x - __uint_as_float(h);   // exactly representable
    unsigned l;
    asm("cvt.rna.tf32.f32 %0, %1;" : "=r"(l) : "f"(r));
    hi = h; lo = l;
}

__device__ __forceinline__ void mma8(float* d, const unsigned* a, const unsigned* b) {
    asm volatile("mma.sync.aligned.m16n8k8.row.col.f32.tf32.tf32.f32 "
                 "{%0,%1,%2,%3}, {%4,%5,%6,%7}, {%8,%9}, {%0,%1,%2,%3};"
                 : "+f"(d[0]), "+f"(d[1]), "+f"(d[2]), "+f"(d[3])
                 : "r"(a[0]), "r"(a[1]), "r"(a[2]), "r"(a[3]),
                   "r"(b[0]), "r"(b[1]));
}

// smem pool layout: [stage(2)][op(4: Ahi,Alo,Whi,Wlo)][8 k][132 cols]
#define POOL_OP   1056              // 8*132
#define POOL_SZ   (2 * 4 * POOL_OP) // 8448 u32 = 33792 B

// Stage one [128 x 8] chunk of A and W into hi/lo tf32 smem (k-major, transposed).
template<bool RELUB>
__device__ __forceinline__ void sts_chunk(float4 pa, float4 pw, unsigned* pool, int s,
                                          const float* __restrict__ B0row, int kk,
                                          int rs, int q4) {
    unsigned* AH = pool + (s * 4 + 0) * POOL_OP;
    unsigned* AL = pool + (s * 4 + 1) * POOL_OP;
    unsigned* WH = pool + (s * 4 + 2) * POOL_OP;
    unsigned* WL = pool + (s * 4 + 3) * POOL_OP;
    float va[4] = {pa.x, pa.y, pa.z, pa.w};
    float vw[4] = {pw.x, pw.y, pw.z, pw.w};
    #pragma unroll
    for (int j = 0; j < 4; j++) {
        float f = va[j];
        if (RELUB) f = fmaxf(f + B0row[kk + q4 + j], 0.f);
        unsigned h, l;
        split_tf32(f, h, l);
        AH[(q4 + j) * 132 + rs] = h;
        AL[(q4 + j) * 132 + rs] = l;
        split_tf32(vw[j], h, l);
        WH[(q4 + j) * 132 + rs] = h;
        WL[(q4 + j) * 132 + rs] = l;
    }
}

// 48 mma per warp over one k8 chunk (3-way tf32 split).
__device__ __forceinline__ void compute_chunk(const unsigned* pool, int s, float acc[4][4][4]) {
    int tid = threadIdx.x, lane = tid & 31, wid = tid >> 5;
    int q = lane & 3, g = lane >> 2;
    int Rb = (wid >> 2) * 64, Cb = (wid & 3) * 32;
    const unsigned* AH = pool + (s * 4 + 0) * POOL_OP;
    const unsigned* AL = pool + (s * 4 + 1) * POOL_OP;
    const unsigned* WH = pool + (s * 4 + 2) * POOL_OP;
    const unsigned* WL = pool + (s * 4 + 3) * POOL_OP;
    unsigned ah[4][4], al[4][4], bh[4][2], bl[4][2];
    #pragma unroll
    for (int nt = 0; nt < 4; nt++) {
        int C0 = Cb + nt * 8 + g;
        bh[nt][0] = WH[q * 132 + C0];
        bh[nt][1] = WH[(q + 4) * 132 + C0];
        bl[nt][0] = WL[q * 132 + C0];
        bl[nt][1] = WL[(q + 4) * 132 + C0];
    }
    #pragma unroll
    for (int mt = 0; mt < 4; mt++) {
        int R0 = Rb + mt * 16 + g;
        ah[mt][0] = AH[q * 132 + R0];
        ah[mt][1] = AH[q * 132 + R0 + 8];
        ah[mt][2] = AH[(q + 4) * 132 + R0];
        ah[mt][3] = AH[(q + 4) * 132 + R0 + 8];
        al[mt][0] = AL[q * 132 + R0];
        al[mt][1] = AL[q * 132 + R0 + 8];
        al[mt][2] = AL[(q + 4) * 132 + R0];
        al[mt][3] = AL[(q + 4) * 132 + R0 + 8];
    }
    #pragma unroll
    for (int mt = 0; mt < 4; mt++)
        #pragma unroll
        for (int nt = 0; nt < 4; nt++) mma8(acc[mt][nt], ah[mt], bh[nt]);
    #pragma unroll
    for (int mt = 0; mt < 4; mt++)
        #pragma unroll
        for (int nt = 0; nt < 4; nt++) mma8(acc[mt][nt], ah[mt], bl[nt]);
    #pragma unroll
    for (int mt = 0; mt < 4; mt++)
        #pragma unroll
        for (int nt = 0; nt < 4; nt++) mma8(acc[mt][nt], al[mt], bh[nt]);
}

// R15-proven pipeline protocol: LDG prefetch -> compute -> STS -> one sync.
template<int NCHUNK, bool RELUB>
__device__ __forceinline__ void mma_mainloop(
    const float* __restrict__ Asrc, int lda,
    const float* __restrict__ Wsrc, int ldw,
    const float* __restrict__ B0row,
    unsigned* pool, float acc[4][4][4])
{
    int tid = threadIdx.x;
    int rs = tid >> 1, q4 = (tid & 1) * 4;
    float4 pa = *(const float4*)(Asrc + rs * lda + q4);
    float4 pw = *(const float4*)(Wsrc + rs * ldw + q4);
    sts_chunk<RELUB>(pa, pw, pool, 0, B0row, 0, rs, q4);
    __syncthreads();
    for (int c = 0; c < NCHUNK; c++) {
        int s = c & 1;
        if (c + 1 < NCHUNK) {
            pa = *(const float4*)(Asrc + rs * lda + (c + 1) * 8 + q4);
            pw = *(const float4*)(Wsrc + rs * ldw + (c + 1) * 8 + q4);
        }
        compute_chunk(pool, s, acc);
        if (c + 1 < NCHUNK) {
            sts_chunk<RELUB>(pa, pw, pool, s ^ 1, B0row, (c + 1) * 8, rs, q4);
            __syncthreads();
        }
    }
}

// ---------------- step 0: code0 = argmin ||x - cb0_k||^2 ----------------
__global__ void k_code0(const float* __restrict__ x,
                        const float* __restrict__ cb0,
                        float* __restrict__ out) {
    __shared__ float s_x[Dq];
    __shared__ float s_v[256];
    __shared__ int   s_i[256];
    int b = blockIdx.x, t = threadIdx.x;
    if (t < Dq) s_x[t] = x[b * Dq + t];
    __syncthreads();
    const float* c = cb0 + t * Dq;
    float acc1 = 0.f, acc2 = 0.f;
    #pragma unroll 8
    for (int d = 0; d < Dq; d++) {
        float cv = c[d];
        acc1 = fmaf(cv, cv, acc1);
        acc2 = fmaf(s_x[d], cv, acc2);
    }
    s_v[t] = acc1 - 2.f * acc2;
    s_i[t] = t;
    __syncthreads();
    for (int s = 128; s > 0; s >>= 1) {
        if (t < s) {
            float v2 = s_v[t + s]; int i2 = s_i[t + s];
            if (v2 < s_v[t] || (v2 == s_v[t] && i2 < s_i[t])) { s_v[t] = v2; s_i[t] = i2; }
        }
        __syncthreads();
    }
    int idx = s_i[0];
    if (t < Dq) {
        float v = cb0[idx * Dq + t];
        g_xhat[b * Dq + t] = v;
        out[OUT_SIDE + b * Dq + t] = v;
    }
    if (t == 0) out[OUT_CODES + b * Mq + 0] = (float)idx;
}

// ---------------- generic 128-deep GEMM core (prep; PROVEN) ----------------
__device__ __forceinline__ void gemm128_core(
    const float* __restrict__ A, int lda,
    const float* __restrict__ W, int ldw,
    const float* __restrict__ addA,
    const float* __restrict__ bias,
    float* __restrict__ out, int ldo,
    int row0, int col0)
{
    __shared__ __align__(16) float As_s[16][132];
    __shared__ __align__(16) float Ws_s[16][132];
    int tid = threadIdx.x;
    int tx = tid & 15, ty = tid >> 4;
    unsigned long long acc[8][4] = {};
    for (int dd = 0; dd < 128; dd += 16) {
        #pragma unroll
        for (int it = 0; it < 8; it++) {
            int idx = tid + it * 256;
            int r = idx >> 4, d = idx & 15;
            As_s[d][r] = A[(row0 + r) * lda + dd + d];
        }
        #pragma unroll
        for (int it = 0; it < 8; it++) {
            int idx = tid + it * 256;
            int c = idx >> 4, d = idx & 15;
            Ws_s[d][c] = W[(col0 + c) * ldw + dd + d];
        }
        __syncthreads();
        #pragma unroll
        for (int h = 0; h < 16; h++) INNER_STEP(As_s, Ws_s);
        __syncthreads();
    }
    #pragma unroll
    for (int i = 0; i < 8; i++) {
        int r = row0 + ty * 8 + i;
        int c0 = col0 + tx * 8;
        float2 p0 = unpk2(acc[i][0]), p1 = unpk2(acc[i][1]);
        float2 p2 = unpk2(acc[i][2]), p3 = unpk2(acc[i][3]);
        float v[8] = {p0.x, p0.y, p1.x, p1.y, p2.x, p2.y, p3.x, p3.y};
        if (addA) {
            #pragma unroll
            for (int j = 0; j < 8; j++) v[j] += addA[r * lda + c0 + j];
        }
        if (bias) {
            #pragma unroll
            for (int j = 0; j < 8; j++) v[j] += bias[c0 + j];
        }
        *(float4*)(&out[r * ldo + c0])     = make_float4(v[0], v[1], v[2], v[3]);
        *(float4*)(&out[r * ldo + c0 + 4]) = make_float4(v[4], v[5], v[6], v[7]);
    }
}

__global__ __launch_bounds__(256) void k_prep_ck(const float* __restrict__ cbs,
                                                 const float* __restrict__ Wc) {
    long z = blockIdx.z;
    const float* cb = cbs + z * (Kq * Dq);
    gemm128_core(cb, Dq, Wc + z * (Dq * 2 * Dq), 2 * Dq,
                 cb, nullptr, g_CkAll + z * (Kq * Dq), Dq,
                 blockIdx.x * 128, 0);
}
__global__ __launch_bounds__(256) void k_prep_a0(const float* __restrict__ W1) {
    long z = blockIdx.z;
    gemm128_core(g_CkAll + z * (Kq * Dq), Dq, W1 + z * (2 * Hq * Dq), Dq,
                 nullptr, nullptr, g_A0All + z * (Kq * Hq), Hq,
                 blockIdx.x * 128, blockIdx.y * 128);
}
__global__ __launch_bounds__(256) void k_prep_xb(const float* __restrict__ Wx,
                                                 const float* __restrict__ bcm) {
    gemm128_core(g_xhat, Dq, Wx, 2 * Dq, nullptr, bcm,
                 g_Xb, Dq, blockIdx.x * 128, 0);
}
__global__ __launch_bounds__(256) void k_prep_b0(const float* __restrict__ W10) {
    gemm128_core(g_Xb, Dq, W10, Dq, nullptr, nullptr,
                 g_B0, Hq, blockIdx.x * 128, blockIdx.y * 128);
}

// ---------------- GEMM A (tensor): Z1 = Ck+Xb + relu(A0+B0) @ W2_0^T ----------------
__global__ __launch_bounds__(256) void gemmA(int m, const float* __restrict__ W20) {
    __shared__ unsigned pool[POOL_SZ];
    int bx = blockIdx.x;
    int b = bx >> 1, k0 = (bx & 1) * 128;
    const float* A0p = g_A0All + (long)m * Kq * Hq + k0 * Hq;
    const float* B0p = g_B0 + b * Hq;
    float acc[4][4][4] = {};
    mma_mainloop<32, true>(A0p, Hq, W20, Hq, B0p, pool, acc);

    int tid = threadIdx.x, lane = tid & 31, wid = tid >> 5;
    int q = lane & 3, g = lane >> 2;
    int Rb = (wid >> 2) * 64, Cb = (wid & 3) * 32;
    const float* Ckm = g_CkAll + (long)m * Kq * Dq;
    const float* xbr = g_Xb + b * Dq;
    #pragma unroll
    for (int mt = 0; mt < 4; mt++) {
        #pragma unroll
        for (int half = 0; half < 2; half++) {
            int lr = Rb + mt * 16 + g + half * 8;
            int krow = k0 + lr;
            const float* ckr = Ckm + krow * Dq;
            float* dst = g_Z1 + (long)(b * Kq + krow) * Dq;
            #pragma unroll
            for (int nt = 0; nt < 4; nt++) {
                int col = Cb + nt * 8 + 2 * q;
                float2 ck = *(const float2*)(ckr + col);
                float2 xb = *(const float2*)(xbr + col);
                float o0 = acc[mt][nt][half * 2 + 0] + ck.x + xb.x;
                float o1 = acc[mt][nt][half * 2 + 1] + ck.y + xb.y;
                *(float2*)(dst + col) = make_float2(o0, o1);
            }
        }
    }
}

// ---------------- GEMM B (tensor): H1 = relu(Z1 @ W1_1^T) ----------------
__global__ __launch_bounds__(256) void gemmB(const float* __restrict__ W11) {
    __shared__ unsigned pool[POOL_SZ];
    int bx = blockIdx.x;
    int row0 = (bx >> 1) * 128, h0 = (bx & 1) * 128;
    const float* Asrc = g_Z1 + (long)row0 * Dq;
    const float* Wp   = W11 + h0 * Dq;
    float acc[4][4][4] = {};
    mma_mainloop<16, false>(Asrc, Dq, Wp, Dq, nullptr, pool, acc);

    int tid = threadIdx.x, lane = tid & 31, wid = tid >> 5;
    int q = lane & 3, g = lane >> 2;
    int Rb = (wid >> 2) * 64, Cb = (wid & 3) * 32;
    #pragma unroll
    for (int mt = 0; mt < 4; mt++) {
        #pragma unroll
        for (int half = 0; half < 2; half++) {
            int lr = Rb + mt * 16 + g + half * 8;
            float* dst = g_H1 + (long)(row0 + lr) * Hq + h0;
            #pragma unroll
            for (int nt = 0; nt < 4; nt++) {
                int col = Cb + nt * 8 + 2 * q;
                float o0 = fmaxf(acc[mt][nt][half * 2 + 0], 0.f);
                float o1 = fmaxf(acc[mt][nt][half * 2 + 1], 0.f);
                *(float2*)(dst + col) = make_float2(o0, o1);
            }
        }
    }
}

// ---------------- GEMM C (tensor): ZF = Z1 + H1 @ W2_1^T + xhat; fused dist ----------
__global__ __launch_bounds__(256) void gemmC(const float* __restrict__ x,
                                             const float* __restrict__ W21) {
    __shared__ unsigned pool[POOL_SZ];
    __shared__ float s_x[Dq];
    __shared__ float s_xh[Dq];
    int bx = blockIdx.x;
    int row0 = bx * 128, b = bx >> 1;
    int tid = threadIdx.x;
    if (tid < Dq) { s_x[tid] = x[b * Dq + tid]; s_xh[tid] = g_xhat[b * Dq + tid]; }
    const float* Asrc = g_H1 + (long)row0 * Hq;
    float acc[4][4][4] = {};
    mma_mainloop<32, false>(Asrc, Hq, W21, Hq, nullptr, pool, acc);

    int lane = tid & 31, wid = tid >> 5;
    int q = lane & 3, g = lane >> 2;
    int Rb = (wid >> 2) * 64, Cb = (wid & 3) * 32;
    int wc = wid & 3;
    // reduction arrays aliased onto stage-0 pool region (free: all warps past last sync,
    // final chunk reads only stage-1).
    float* s_ssq = (float*)pool;            // [128][5]
    float* s_sxz = (float*)pool + 128 * 5;  // [128][5]
    #pragma unroll
    for (int mt = 0; mt < 4; mt++) {
        #pragma unroll
        for (int half = 0; half < 2; half++) {
            int lr = Rb + mt * 16 + g + half * 8;
            const float* z1r = g_Z1 + (long)(row0 + lr) * Dq;
            float* dst = g_ZF + (long)(row0 + lr) * Dq;
            float ssq = 0.f, sxz = 0.f;
            #pragma unroll
            for (int nt = 0; nt < 4; nt++) {
                int col = Cb + nt * 8 + 2 * q;
                float2 z1 = *(const float2*)(z1r + col);
                float o0 = acc[mt][nt][half * 2 + 0] + z1.x + s_xh[col];
                float o1 = acc[mt][nt][half * 2 + 1] + z1.y + s_xh[col + 1];
                *(float2*)(dst + col) = make_float2(o0, o1);
                ssq = fmaf(o0, o0, fmaf(o1, o1, ssq));
                sxz = fmaf(s_x[col], o0, fmaf(s_x[col + 1], o1, sxz));
            }
            // quad reduce (lanes sharing g cover the warp's 32-col stripe)
            ssq += __shfl_xor_sync(0xffffffffu, ssq, 1);
            ssq += __shfl_xor_sync(0xffffffffu, ssq, 2);
            sxz += __shfl_xor_sync(0xffffffffu, sxz, 1);
            sxz += __shfl_xor_sync(0xffffffffu, sxz, 2);
            if (q == 0) {
                s_ssq[lr * 5 + wc] = ssq;
                s_sxz[lr * 5 + wc] = sxz;
            }
        }
    }
    __syncthreads();
    if (tid < 128) {
        float ssq = 0.f, sxz = 0.f;
        #pragma unroll
        for (int w = 0; w < 4; w++) { ssq += s_ssq[tid * 5 + w]; sxz += s_sxz[tid * 5 + w]; }
        g_dist[row0 + tid] = ssq - 2.f * sxz;
    }
}

// ---------------- select ----------------
__global__ void k_select(float* __restrict__ out, int m) {
    __shared__ float s_v[256];
    __shared__ int   s_i[256];
    int b = blockIdx.x, t = threadIdx.x;
    s_v[t] = g_dist[b * Kq + t];
    s_i[t] = t;
    __syncthreads();
    for (int s = 128; s > 0; s >>= 1) {
        if (t < s) {
            float v2 = s_v[t + s]; int i2 = s_i[t + s];
            if (v2 < s_v[t] || (v2 == s_v[t] && i2 < s_i[t])) { s_v[t] = v2; s_i[t] = i2; }
        }
        __syncthreads();
    }
    int idx = s_i[0];
    if (t < Dq) {
        float v = g_ZF[(b * Kq + idx) * Dq + t];
        g_xhat[b * Dq + t] = v;
        out[OUT_SIDE + (m + 1) * (BSq * Dq) + b * Dq + t] = v;
        if (m == Mq - 2) out[b * Dq + t] = v;
    }
    if (t == 0) out[OUT_CODES + b * Mq + m + 1] = (float)idx;
}

// ---------------- launch (pure kernel launches) ----------------
extern "C" void kernel_launch(void* const* d_in, const int* in_sizes, int n_in,
                              void* d_out, int out_size) {
    const float* x   = (const float*)d_in[0];   // [1024,128]
    const float* cb0 = (const float*)d_in[1];   // [256,128]
    const float* cbs = (const float*)d_in[2];   // [7,256,128]
    const float* Wc  = (const float*)d_in[3];   // [7,128,256]
    const float* bc  = (const float*)d_in[4];   // [7,128]
    const float* W1  = (const float*)d_in[5];   // [7,2,256,128]
    const float* W2  = (const float*)d_in[6];   // [7,2,128,256]
    float* out = (float*)d_out;

    k_code0<<<BSq, 256>>>(x, cb0, out);

    // Hoisted (xhat-independent) per-m precomputation.
    k_prep_ck<<<dim3(2, 1, Mq - 1), 256>>>(cbs, Wc);
    k_prep_a0<<<dim3(2, 2, Mq - 1), 256>>>(W1);

    for (int m = 0; m < Mq - 1; m++) {
        const float* Wcm = Wc + m * Dq * (2 * Dq);
        const float* bcm = bc + m * Dq;
        const float* W10 = W1 + (m * 2 + 0) * Hq * Dq;
        const float* W11 = W1 + (m * 2 + 1) * Hq * Dq;
        const float* W20 = W2 + (m * 2 + 0) * Dq * Hq;
        const float* W21 = W2 + (m * 2 + 1) * Dq * Hq;

        k_prep_xb<<<dim3(8, 1, 1), 256>>>(Wcm + Dq, bcm);
        k_prep_b0<<<dim3(8, 2, 1), 256>>>(W10);

        gemmA<<<2048, 256>>>(m, W20);
        gemmB<<<4096, 256>>>(W11);
        gemmC<<<2048, 256>>>(x, W21);
        k_select<<<BSq, 256>>>(out, m);
    }
}